// round 4
// baseline (speedup 1.0000x reference)
#include <cuda_runtime.h>
#include <cstdint>

// CSCFCLayer: out[b][n] = sum_{f<64} x[b][(n+f)%C] * kernel[(n+f)%C][n] + bias[n]
// B=128, C=N=8192, F=64, fp32.
//
// v4: v3's occupancy structure (grid=256, 2 CTAs/SM) + v2's instruction-efficient
// hot loop (duplicated weights in smem -> no mov packs).
//  - Per CTA: NT=64 cols, BT=64 batches, 512 threads, 16 warps (8 col-groups x 2 halves).
//  - ws: [128 rows][64 f2] duplicated weights (64KB), band mask folded into fill.
//  - xs: [128 rows][32 f2] batch-paired x (34KB), filled via cp.async (overlaps ws LDGs).
//  - Hot step: LDS.64 x-pair + 4x LDS.128 dup-weights + 8 fma.rn.f32x2.
//  - Epilogue: 2-way partial reduce through smem, coalesced stores + bias.

#define CDIM 8192
#define NDIM 8192
#define NT 64
#define BT 64
#define THREADS 512
#define NWARPS 16
#define CROWS 128
#define WS_STRIDE 128          // floats per ws row (64 float2, 512B)
#define XS_STRIDE 66           // floats per xs row (33 float2)
#define HALF_STEPS 36

__device__ __forceinline__ void fma2(unsigned long long& d,
                                     unsigned long long a,
                                     unsigned long long b) {
    asm("fma.rn.f32x2 %0, %1, %2, %0;" : "+l"(d) : "l"(a), "l"(b));
}

__device__ __forceinline__ void cpasync4(unsigned dst, const void* src) {
    asm volatile("cp.async.ca.shared.global [%0], [%1], 4;"
                 :: "r"(dst), "l"(src) : "memory");
}

extern "C" __global__ void __launch_bounds__(THREADS, 2)
cscfc_kernel(const float* __restrict__ x,
             const float* __restrict__ w,
             const float* __restrict__ bias,
             float* __restrict__ out)
{
    extern __shared__ float smem[];
    float* ws = smem;                          // CROWS * WS_STRIDE (dup'd band weights)
    float* xs = smem + CROWS * WS_STRIDE;      // CROWS * XS_STRIDE (paired x)

    const int tid  = threadIdx.x;
    const int lane = tid & 31;
    const int wid  = tid >> 5;
    const int ng   = wid & 7;                  // column group (8 cols)
    const int half = wid >> 3;                 // c-window half
    const int tile = blockIdx.x & 127;
    const int bh   = blockIdx.x >> 7;
    const int n0   = tile * NT;
    const int b0   = bh * BT;

    const unsigned xs_u = (unsigned)__cvta_generic_to_shared(xs);

    // ---- xs fill via cp.async (issued first; overlaps the ws LDGs below).
    //      xs[cl] f2-slot q = (x[b0+q][c], x[b0+q+32][c]), c = (n0+cl)%C. ----
#pragma unroll
    for (int k = 0; k < 16; ++k) {
        const int idx = tid + k * THREADS;
        const int cl  = idx & 127;             // lanes vary cl -> coalesced gmem reads
        const int b   = idx >> 7;              // 0..63
        const int c   = (n0 + cl) & (CDIM - 1);
        const unsigned dst =
            xs_u + (unsigned)(cl * XS_STRIDE + (b & 31) * 2 + (b >> 5)) * 4u;
        cpasync4(dst, x + (size_t)(b0 + b) * CDIM + c);
    }
    asm volatile("cp.async.commit_group;" ::: "memory");

    // ---- ws fill: row cl holds kernel[(n0+cl)%C][n0+nl] duplicated at f2 slot nl,
    //      zero where f = cl - nl outside [0,64). 16 independent LDGs/thread. ----
#pragma unroll
    for (int i = 0; i < CROWS / NWARPS; ++i) {
        const int cl = wid + i * NWARPS;
        const int r  = (n0 + cl) & (CDIM - 1);
        const float* krow = w + (size_t)r * NDIM + n0;
        const float k0 = krow[lane];
        const float k1 = krow[lane + 32];
        const int f0 = cl - lane;
        const int f1 = cl - (lane + 32);
        const float v0 = (f0 >= 0 && f0 < 64) ? k0 : 0.0f;
        const float v1 = (f1 >= 0 && f1 < 64) ? k1 : 0.0f;
        float2* wrow = (float2*)(ws + cl * WS_STRIDE);
        wrow[lane]      = make_float2(v0, v0);
        wrow[lane + 32] = make_float2(v1, v1);
    }
    asm volatile("cp.async.wait_group 0;" ::: "memory");
    __syncthreads();

    // ---- Compute: warp (ng, half): cols n0+ng*8..+7, 36 c-steps. ----
    unsigned long long acc[8];
#pragma unroll
    for (int j = 0; j < 8; ++j) acc[j] = 0ULL;

    const int cl0 = ng * 8 + half * HALF_STEPS;
    const float* xrow = xs + cl0 * XS_STRIDE + lane * 2;
    const float* wrow = ws + cl0 * WS_STRIDE + ng * 16;   // 8 f2 = 16 floats per group
#pragma unroll 4
    for (int i = 0; i < HALF_STEPS; ++i) {
        const unsigned long long xp = *(const unsigned long long*)xrow;  // (b, b+32)
        const ulonglong2* wv = (const ulonglong2*)wrow;
        const ulonglong2 w0 = wv[0];     // LDS.128 broadcast: cols 0,1 dup'd
        const ulonglong2 w1 = wv[1];
        const ulonglong2 w2 = wv[2];
        const ulonglong2 w3 = wv[3];
        fma2(acc[0], xp, w0.x);
        fma2(acc[1], xp, w0.y);
        fma2(acc[2], xp, w1.x);
        fma2(acc[3], xp, w1.y);
        fma2(acc[4], xp, w2.x);
        fma2(acc[5], xp, w2.y);
        fma2(acc[6], xp, w3.x);
        fma2(acc[7], xp, w3.y);
        xrow += XS_STRIDE;
        wrow += WS_STRIDE;
    }
    __syncthreads();

    // ---- Epilogue: reduce the two halves through smem, then coalesced stores. ----
    float* os = smem;   // [64 b][65] floats, aliases ws
    if (half == 0) {
#pragma unroll
        for (int j = 0; j < 8; ++j) {
            const int nl = ng * 8 + j;
            os[lane * 65 + nl]        = __uint_as_float((unsigned)(acc[j] & 0xffffffffu));
            os[(lane + 32) * 65 + nl] = __uint_as_float((unsigned)(acc[j] >> 32));
        }
    }
    __syncthreads();
    if (half == 1) {
#pragma unroll
        for (int j = 0; j < 8; ++j) {
            const int nl = ng * 8 + j;
            os[lane * 65 + nl]        += __uint_as_float((unsigned)(acc[j] & 0xffffffffu));
            os[(lane + 32) * 65 + nl] += __uint_as_float((unsigned)(acc[j] >> 32));
        }
    }
    __syncthreads();

#pragma unroll
    for (int t = tid; t < BT * NT; t += THREADS) {   // 8 iters
        const int nl = t & (NT - 1);
        const int bl = t >> 6;
        out[(size_t)(b0 + bl) * NDIM + n0 + nl] = os[bl * 65 + nl] + bias[n0 + nl];
    }
}

extern "C" void kernel_launch(void* const* d_in, const int* in_sizes, int n_in,
                              void* d_out, int out_size) {
    const float* x    = (const float*)d_in[0];
    const float* w    = (const float*)d_in[1];
    const float* bias = (const float*)d_in[2];
    float* out        = (float*)d_out;

    const size_t smem_bytes =
        (size_t)(CROWS * WS_STRIDE + CROWS * XS_STRIDE) * sizeof(float);
    cudaFuncSetAttribute(cscfc_kernel,
                         cudaFuncAttributeMaxDynamicSharedMemorySize,
                         (int)smem_bytes);
    cscfc_kernel<<<256, THREADS, smem_bytes>>>(x, w, bias, out);
}

// round 5
// speedup vs baseline: 1.1626x; 1.1626x over previous
#include <cuda_runtime.h>
#include <cstdint>

// CSCFCLayer: out[b][n] = sum_{f<64} x[b][(n+f)%C] * kernel[(n+f)%C][n] + bias[n]
// B=128, C=N=8192, F=64, fp32.
//
// v5: column-packed f32x2 (duplicate moves to x: 4 MOV per 8 FMA2, weights plain).
//  - Grid 256 (128 col-tiles x 2 batch halves), CTA: 64 cols x 64 batches, 512 thr,
//    16 warps = 8 col-groups x 2 c-halves, 2 CTAs/SM.
//  - ws [128][64] plain fp32 (32KB, band-masked zeros); xs [128][65] transposed x
//    (33KB, stride 65 -> conflict-free lanes-vary-b reads AND lanes-vary-c fill stores).
//  - Hot step: 2 LDS.32 x + 2 dup + 2 LDS.128 w (broadcast) + 8 fma.rn.f32x2.
//  - Epilogue: half0 -> smem floats (conflict-free), half1 adds + bias, STG.128.

#define CDIM 8192
#define NDIM 8192
#define NT 64
#define BT 64
#define THREADS 512
#define NWARPS 16
#define CROWS 128
#define WS_STRIDE 64
#define XS_STRIDE 65
#define OS_STRIDE 65
#define HALF_STEPS 36

__device__ __forceinline__ void fma2(unsigned long long& d,
                                     unsigned long long a,
                                     unsigned long long b) {
    asm("fma.rn.f32x2 %0, %1, %2, %0;" : "+l"(d) : "l"(a), "l"(b));
}

__device__ __forceinline__ unsigned long long dup2(float v) {
    unsigned long long r;
    unsigned u = __float_as_uint(v);
    asm("mov.b64 %0, {%1, %1};" : "=l"(r) : "r"(u));
    return r;
}

__device__ __forceinline__ float2 unpack2(unsigned long long v) {
    float2 r;
    asm("mov.b64 {%0, %1}, %2;" : "=f"(r.x), "=f"(r.y) : "l"(v));
    return r;
}

extern "C" __global__ void __launch_bounds__(THREADS, 2)
cscfc_kernel(const float* __restrict__ x,
             const float* __restrict__ w,
             const float* __restrict__ bias,
             float* __restrict__ out)
{
    extern __shared__ float smem[];
    float* ws = smem;                          // [128][64] plain band weights
    float* xs = smem + CROWS * WS_STRIDE;      // [128][65] transposed x

    const int tid  = threadIdx.x;
    const int lane = tid & 31;
    const int wid  = tid >> 5;
    const int ng   = wid & 7;                  // column group (8 cols)
    const int half = wid >> 3;                 // c-window half
    const int tile = blockIdx.x & 127;
    const int bh   = blockIdx.x >> 7;
    const int n0   = tile * NT;
    const int b0   = bh * BT;

    // ---- xs fill: warp handles 4 batches; lanes vary c -> coalesced LDG,
    //      STS banks (c + b) % 32 -> conflict-free. ----
    {
        const int bbase = wid * 4;
#pragma unroll
        for (int j = 0; j < 4; ++j) {
            const int b = bbase + j;
            const float* xrow = x + (size_t)(b0 + b) * CDIM;
#pragma unroll
            for (int k = 0; k < 4; ++k) {
                const int cl = k * 32 + lane;
                xs[cl * XS_STRIDE + b] = xrow[(n0 + cl) & (CDIM - 1)];
            }
        }
    }

    // ---- ws fill: row cl = kernel[(n0+cl)%C][n0+nl], zero where f=cl-nl not in [0,64). ----
#pragma unroll
    for (int i = 0; i < CROWS / NWARPS; ++i) {
        const int cl = wid + i * NWARPS;
        const int r  = (n0 + cl) & (CDIM - 1);
        const float* krow = w + (size_t)r * NDIM + n0;
        const float k0 = krow[lane];
        const float k1 = krow[lane + 32];
        const int f0 = cl - lane;
        const int f1 = cl - lane - 32;
        ws[cl * WS_STRIDE + lane]      = (f0 >= 0 && f0 < 64) ? k0 : 0.0f;
        ws[cl * WS_STRIDE + lane + 32] = (f1 >= 0 && f1 < 64) ? k1 : 0.0f;
    }
    __syncthreads();

    // ---- Compute: warp (ng, half): cols n0+ng*8..+7, batches lane & lane+32,
    //      36 c-steps. acc[h][p] packs (col 2p, col 2p+1) for batch lane+32h. ----
    unsigned long long acc[2][4];
#pragma unroll
    for (int h = 0; h < 2; ++h)
#pragma unroll
        for (int p = 0; p < 4; ++p) acc[h][p] = 0ULL;

    const int cl0 = ng * 8 + half * HALF_STEPS;
    const float* xp = xs + cl0 * XS_STRIDE + lane;
    const float* wp = ws + cl0 * WS_STRIDE + ng * 8;
#pragma unroll 2
    for (int i = 0; i < HALF_STEPS; ++i) {
        const unsigned long long xa = dup2(xp[0]);     // batch = lane
        const unsigned long long xb = dup2(xp[32]);    // batch = lane+32
        const ulonglong2 w01 = *(const ulonglong2*)(wp);      // cols 0..3 (broadcast)
        const ulonglong2 w23 = *(const ulonglong2*)(wp + 4);  // cols 4..7
        fma2(acc[0][0], xa, w01.x);
        fma2(acc[0][1], xa, w01.y);
        fma2(acc[0][2], xa, w23.x);
        fma2(acc[0][3], xa, w23.y);
        fma2(acc[1][0], xb, w01.x);
        fma2(acc[1][1], xb, w01.y);
        fma2(acc[1][2], xb, w23.x);
        fma2(acc[1][3], xb, w23.y);
        xp += XS_STRIDE;
        wp += WS_STRIDE;
    }
    __syncthreads();

    // ---- Epilogue: half0 stages partials as floats (conflict-free stride 65);
    //      half1 adds own acc + partner + bias, stores via STG.128. ----
    float* os = smem;   // [64 b][65]
    if (half == 0) {
#pragma unroll
        for (int h = 0; h < 2; ++h) {
            const int b = lane + 32 * h;
#pragma unroll
            for (int p = 0; p < 4; ++p) {
                const float2 v = unpack2(acc[h][p]);
                os[b * OS_STRIDE + ng * 8 + 2 * p]     = v.x;
                os[b * OS_STRIDE + ng * 8 + 2 * p + 1] = v.y;
            }
        }
    }
    __syncthreads();
    if (half == 1) {
        const float4 bz0 = *(const float4*)(bias + n0 + ng * 8);
        const float4 bz1 = *(const float4*)(bias + n0 + ng * 8 + 4);
        const float bs[8] = {bz0.x, bz0.y, bz0.z, bz0.w, bz1.x, bz1.y, bz1.z, bz1.w};
#pragma unroll
        for (int h = 0; h < 2; ++h) {
            const int b = lane + 32 * h;
            float v[8];
#pragma unroll
            for (int p = 0; p < 4; ++p) {
                const float2 a = unpack2(acc[h][p]);
                v[2 * p]     = a.x + os[b * OS_STRIDE + ng * 8 + 2 * p]     + bs[2 * p];
                v[2 * p + 1] = a.y + os[b * OS_STRIDE + ng * 8 + 2 * p + 1] + bs[2 * p + 1];
            }
            float4* o = (float4*)(out + (size_t)(b0 + b) * NDIM + n0 + ng * 8);
            o[0] = make_float4(v[0], v[1], v[2], v[3]);
            o[1] = make_float4(v[4], v[5], v[6], v[7]);
        }
    }
}

extern "C" void kernel_launch(void* const* d_in, const int* in_sizes, int n_in,
                              void* d_out, int out_size) {
    const float* x    = (const float*)d_in[0];
    const float* w    = (const float*)d_in[1];
    const float* bias = (const float*)d_in[2];
    float* out        = (float*)d_out;

    const size_t smem_bytes =
        (size_t)(CROWS * WS_STRIDE + CROWS * XS_STRIDE) * sizeof(float);
    cudaFuncSetAttribute(cscfc_kernel,
                         cudaFuncAttributeMaxDynamicSharedMemorySize,
                         (int)smem_bytes);
    cscfc_kernel<<<256, THREADS, smem_bytes>>>(x, w, bias, out);
}

// round 7
// speedup vs baseline: 1.1830x; 1.0175x over previous
#include <cuda_runtime.h>
#include <mma.h>
#include <cstdint>

using namespace nvcuda;

// CSCFCLayer: out[b][n] = sum_{f<64} x[b][(n+f)%C] * kernel[(n+f)%C][n] + bias[n]
// B=128, C=N=8192, F=64, fp32.
//
// v7: TF32 wmma (HMMA — works on base sm_103 target; tcgen05 is 103a-only and the
// harness builds compute_103 PTX).
// Per tile n0 (64 cols): D[128b x 64n] = A[128b x 128k] @ B, B[k][n] = banded weights.
//  - A smem [128][132] fp32 = raw x window, filled via cp.async (no conversion).
//  - B smem [64 n][132 k] fp32 (col-major k x n for wmma), band mask via FSEL.
//  - 16 warps: warp (mw, nw) owns 32 rows x 16 cols = 2 m16n16k8 acc frags, 16 K-steps.
//  - tf32 rounding only on fragment registers (__float_to_tf32).
//  - Epilogue: store_matrix_sync -> smem [128][68], +bias, coalesced float4 STG.

#define CDIM 8192
#define NDIM 8192
#define NT 64
#define THREADS 512
#define ASTRIDE 132
#define BSTRIDE 132
#define OSTRIDE 68
#define A_FLOATS (128 * ASTRIDE)
#define SMEM_NEED ((A_FLOATS + 64 * BSTRIDE) * 4)

extern "C" __global__ void __launch_bounds__(THREADS, 1)
cscfc_wmma_kernel(const float* __restrict__ x,
                  const float* __restrict__ w,
                  const float* __restrict__ bias,
                  float* __restrict__ out)
{
    extern __shared__ float sm[];
    float* As = sm;               // [128][ASTRIDE] x window
    float* Bs = sm + A_FLOATS;    // [64][BSTRIDE]  banded weights, [n][k]

    const int tid = threadIdx.x;
    const int n0  = blockIdx.x * NT;

    // ---- A fill: A[b][cl] = x[b][(n0+cl)%C], raw fp32 via 16B cp.async.
    //      4096 float4: idx -> b = idx>>5, q = idx&31 (float4 col). Wrap is
    //      float4-aligned (window crosses 8192 only at a multiple of 4). ----
    {
        const unsigned as_u = (unsigned)__cvta_generic_to_shared(As);
#pragma unroll
        for (int it = 0; it < 8; ++it) {
            const int idx = tid + it * THREADS;
            const int b = idx >> 5;
            const int q = idx & 31;
            const int c = (n0 + q * 4) & (CDIM - 1);
            const unsigned dst = as_u + (unsigned)(b * ASTRIDE + q * 4) * 4u;
            const float* src = x + (size_t)b * CDIM + c;
            asm volatile("cp.async.cg.shared.global [%0], [%1], 16;"
                         :: "r"(dst), "l"(src) : "memory");
        }
        asm volatile("cp.async.commit_group;" ::: "memory");
    }

    // ---- B fill: Bs[n][cl] = kernel[(n0+cl)%C][n0+n] if f = cl-n in [0,64) else 0.
    //      2048 float4 gmem reads (coalesced along n), scattered STS.32. ----
#pragma unroll
    for (int it = 0; it < 4; ++it) {
        const int idx = tid + it * THREADS;
        const int cl = idx >> 4;
        const int n  = (idx & 15) * 4;
        const int r  = (n0 + cl) & (CDIM - 1);
        const float4 wv = *(const float4*)(w + (size_t)r * NDIM + n0 + n);
        const float v[4] = {wv.x, wv.y, wv.z, wv.w};
#pragma unroll
        for (int j = 0; j < 4; ++j) {
            const unsigned f = (unsigned)(cl - (n + j));
            Bs[(n + j) * BSTRIDE + cl] = (f < 64u) ? v[j] : 0.0f;
        }
    }
    asm volatile("cp.async.wait_group 0;" ::: "memory");
    __syncthreads();

    // ---- MMA: warp (mw, nw): rows mw*32..+31, cols nw*16..+15. ----
    const int wid = tid >> 5;
    const int mw  = wid & 3;
    const int nw  = wid >> 2;

    wmma::fragment<wmma::accumulator, 16, 16, 8, float> c0, c1;
    wmma::fill_fragment(c0, 0.0f);
    wmma::fill_fragment(c1, 0.0f);

#pragma unroll 4
    for (int k8 = 0; k8 < 16; ++k8) {
        wmma::fragment<wmma::matrix_a, 16, 16, 8, wmma::precision::tf32, wmma::row_major> a0, a1;
        wmma::fragment<wmma::matrix_b, 16, 16, 8, wmma::precision::tf32, wmma::col_major> bf;
        wmma::load_matrix_sync(a0, As + (mw * 32) * ASTRIDE + k8 * 8, ASTRIDE);
        wmma::load_matrix_sync(a1, As + (mw * 32 + 16) * ASTRIDE + k8 * 8, ASTRIDE);
        wmma::load_matrix_sync(bf, Bs + (nw * 16) * BSTRIDE + k8 * 8, BSTRIDE);
#pragma unroll
        for (int i = 0; i < a0.num_elements; ++i) {
            a0.x[i] = wmma::__float_to_tf32(a0.x[i]);
            a1.x[i] = wmma::__float_to_tf32(a1.x[i]);
        }
#pragma unroll
        for (int i = 0; i < bf.num_elements; ++i)
            bf.x[i] = wmma::__float_to_tf32(bf.x[i]);
        wmma::mma_sync(c0, a0, bf, c0);
        wmma::mma_sync(c1, a1, bf, c1);
    }
    __syncthreads();   // all warps done reading As/Bs before overlaying os

    // ---- Stage results: os[128][OSTRIDE] overlays As. ----
    float* os = sm;
    wmma::store_matrix_sync(os + (mw * 32) * OSTRIDE + nw * 16, c0, OSTRIDE,
                            wmma::mem_row_major);
    wmma::store_matrix_sync(os + (mw * 32 + 16) * OSTRIDE + nw * 16, c1, OSTRIDE,
                            wmma::mem_row_major);
    __syncthreads();

    // ---- Output: + bias, coalesced float4 stores. ----
#pragma unroll
    for (int it = 0; it < 4; ++it) {
        const int idx = tid + it * THREADS;
        const int b = idx >> 4;
        const int q = (idx & 15) * 4;
        const float4 v  = *(const float4*)(os + b * OSTRIDE + q);
        const float4 bb = *(const float4*)(bias + n0 + q);
        float4 o;
        o.x = v.x + bb.x;
        o.y = v.y + bb.y;
        o.z = v.z + bb.z;
        o.w = v.w + bb.w;
        *(float4*)(out + (size_t)b * NDIM + n0 + q) = o;
    }
}

extern "C" void kernel_launch(void* const* d_in, const int* in_sizes, int n_in,
                              void* d_out, int out_size) {
    const float* x    = (const float*)d_in[0];
    const float* w    = (const float*)d_in[1];
    const float* bias = (const float*)d_in[2];
    float* out        = (float*)d_out;

    cudaFuncSetAttribute(cscfc_wmma_kernel,
                         cudaFuncAttributeMaxDynamicSharedMemorySize, SMEM_NEED);
    cscfc_wmma_kernel<<<NDIM / NT, THREADS, SMEM_NEED>>>(x, w, bias, out);
}